// round 15
// baseline (speedup 1.0000x reference)
#include <cuda_runtime.h>
#include <cuda_bf16.h>
#include <math.h>
#include <cstdint>

// ---------------- problem constants ----------------
#define PB 256
#define PN 128
#define PD 768
#define PE 3
#define PS 44
#define PES 132
#define PESP 136          // padded combine ld
#define PMUP 144          // padded mu_cat ld
#define PH 1024
#define PMAXS 88
#define PM_TOK (PB*PN)
#define PM_FFN (PB*PS)

// ---------------- scratch (device globals) ----------------
__device__ float g_slot_input[PB * 769];
__device__ float g_slot_bias [PB * PD];
__device__ float g_img_n     [PM_TOK * PD];
__device__ float g_dot       [PM_TOK];
__device__ float g_mu_cat    [PD * PMUP];
__device__ float g_logits    [PM_TOK * PES];
__device__ float g_dispT     [PB * PES * PN];
__device__ float g_combine   [PM_TOK * PESP];
__device__ float g_slot_in   [PB * PES * PD];
__device__ float g_hbuf      [PB * PES * PH];
__device__ float g_slot_out  [PB * PES * PD];
__device__ float g_cls_h     [PB * 4 * PD];
__device__ float g_part      [3 * PB * 4 * PD];

// ---------------- helpers ----------------
__device__ __forceinline__ float gelu_exact(float x) {
    return 0.5f * x * (1.0f + erff(x * 0.70710678118654752440f));
}
__device__ __forceinline__ unsigned long long bcast2(float x) {
    unsigned long long r;
    asm("mov.b64 %0, {%1, %1};" : "=l"(r) : "r"(__float_as_uint(x)));
    return r;
}
__device__ __forceinline__ void ffma2(unsigned long long& c,
                                      unsigned long long a,
                                      unsigned long long b) {
    asm("fma.rn.f32x2 %0, %1, %2, %0;" : "+l"(c) : "l"(a), "l"(b));
}
__device__ __forceinline__ uint32_t smem_u32(const void* p) {
    uint32_t a;
    asm("{ .reg .u64 t; cvta.to.shared.u64 t, %1; cvt.u32.u64 %0, t; }" : "=r"(a) : "l"(p));
    return a;
}
__device__ __forceinline__ void cp_async16(uint32_t dst, const void* src) {
    asm volatile("cp.async.cg.shared.global [%0], [%1], 16;" :: "r"(dst), "l"(src));
}
#define CP_COMMIT() asm volatile("cp.async.commit_group;" ::: "memory")
#define CP_WAIT0()  asm volatile("cp.async.wait_group 0;" ::: "memory")

#define EP_STORE     0
#define EP_BIAS      1
#define EP_BIAS_GELU 2
#define EP_LOGITS    3

// ---------------- guarded FFMA2 SGEMM (unchanged from R14) ----------------
template<bool GUARD, bool MAP_ROWS, int EP>
__global__ __launch_bounds__(256)
void fgemm2(const float* __restrict__ A, const float* __restrict__ B,
            float* __restrict__ C,
            int M, int N, int K, int lda, int ldb, int ldc,
            long long sA, long long sB, long long sC,
            const float* __restrict__ v1, const float* __restrict__ v2,
            const float* __restrict__ scale_ptr, int biasStride,
            int kChunk)
{
    const int z = blockIdx.z;
    const float* Ab = A + (long long)z * sA;
    const float* Bb = B + (long long)z * sB;
    float*       Cb = C + (long long)z * sC;

    int ks = 0, ke = K;
    if (kChunk > 0) {
        ks = z * kChunk;
        ke = (K < ks + kChunk) ? K : (ks + kChunk);
    }

    __shared__ __align__(16) float As[2][16][128];
    __shared__ __align__(16) float Bs[2][16][128];

    const int tid = threadIdx.x;
    const int tx = tid & 15;
    const int ty = tid >> 4;
    const int m0 = blockIdx.x * 128;
    const int n0 = blockIdx.y * 128;

    unsigned long long acc[8][4];
    #pragma unroll
    for (int i = 0; i < 8; i++)
        #pragma unroll
        for (int p = 0; p < 4; p++) acc[i][p] = 0ull;

    const int a_r  = tid >> 1;
    const int a_c8 = (tid & 1) * 8;
    const int t_k = tid >> 4;
    const int t_c = (tid & 15) * 8;

    long long a_off = 0;
    bool a_ok = true;
    {
        const int gm = m0 + a_r;
        a_ok = !GUARD || (gm < M);
        int rr = gm;
        if (MAP_ROWS) rr = (gm / 44) * PES + z * PS + (gm % 44);
        a_off = (long long)rr * lda;
    }
    const bool aAlign = ((a_off & 3) == 0);
    const bool bColsOk = !GUARD || (n0 + 128 <= N);

    const uint32_t bsu0 = smem_u32(&Bs[0][t_k][t_c]);
    const uint32_t bsu1 = smem_u32(&Bs[1][t_k][t_c]);

    const int nk = (ke - ks + 15) >> 4;
    float va[8], vb[8];

    auto load_a = [&](int k0) {
        const bool kfull = !GUARD || (k0 + 16 <= ke);
        if ((!GUARD) || (a_ok && aAlign && kfull)) {
            const float4 u0 = *reinterpret_cast<const float4*>(Ab + a_off + k0 + a_c8);
            const float4 u1 = *reinterpret_cast<const float4*>(Ab + a_off + k0 + a_c8 + 4);
            va[0]=u0.x; va[1]=u0.y; va[2]=u0.z; va[3]=u0.w;
            va[4]=u1.x; va[5]=u1.y; va[6]=u1.z; va[7]=u1.w;
        } else {
            #pragma unroll
            for (int j = 0; j < 8; j++) {
                const int k = k0 + a_c8 + j;
                va[j] = (a_ok && k < ke) ? Ab[a_off + k] : 0.f;
            }
        }
    };
    auto store_a = [&](int buf) {
        #pragma unroll
        for (int j = 0; j < 8; j++) As[buf][a_c8 + j][a_r] = va[j];
    };
    auto load_b_guard = [&](int k0) {
        const int gk = k0 + t_k;
        const long long ro = (long long)gk * ldb + n0 + t_c;
        if ((gk < ke) && bColsOk && ((ro & 3) == 0)) {
            const float4 u0 = *reinterpret_cast<const float4*>(Bb + ro);
            const float4 u1 = *reinterpret_cast<const float4*>(Bb + ro + 4);
            vb[0]=u0.x; vb[1]=u0.y; vb[2]=u0.z; vb[3]=u0.w;
            vb[4]=u1.x; vb[5]=u1.y; vb[6]=u1.z; vb[7]=u1.w;
        } else {
            #pragma unroll
            for (int j = 0; j < 8; j++) {
                const int gn = n0 + t_c + j;
                vb[j] = (gk < ke && gn < N) ? Bb[(long long)gk * ldb + gn] : 0.f;
            }
        }
    };
    auto store_b_guard = [&](int buf) {
        *reinterpret_cast<float4*>(&Bs[buf][t_k][t_c])     = make_float4(vb[0], vb[1], vb[2], vb[3]);
        *reinterpret_cast<float4*>(&Bs[buf][t_k][t_c + 4]) = make_float4(vb[4], vb[5], vb[6], vb[7]);
    };
    auto cp_b = [&](int k0, int buf) {
        const int gk = k0 + t_k;
        const float* src = Bb + (long long)gk * ldb + n0 + t_c;
        const uint32_t d = buf ? bsu1 : bsu0;
        cp_async16(d, src);
        cp_async16(d + 16, src + 4);
    };

    load_a(ks);
    if (GUARD) {
        load_b_guard(ks);
        store_a(0);
        store_b_guard(0);
    } else {
        cp_b(ks, 0);
        CP_COMMIT();
        store_a(0);
        CP_WAIT0();
    }
    __syncthreads();

    for (int kt = 0; kt < nk; kt++) {
        const int cur = kt & 1;
        const bool more = (kt + 1 < nk);
        if (more) {
            const int k0n = ks + ((kt + 1) << 4);
            if (!GUARD) { cp_b(k0n, cur ^ 1); CP_COMMIT(); }
            else load_b_guard(k0n);
            load_a(k0n);
        }
        float4 ca0 = *reinterpret_cast<const float4*>(&As[cur][0][ty * 8]);
        float4 ca1 = *reinterpret_cast<const float4*>(&As[cur][0][ty * 8 + 4]);
        ulonglong2 cbl = *reinterpret_cast<const ulonglong2*>(&Bs[cur][0][tx * 4]);
        ulonglong2 cbh = *reinterpret_cast<const ulonglong2*>(&Bs[cur][0][64 + tx * 4]);
        #pragma unroll
        for (int k = 0; k < 16; k++) {
            const int kn = (k + 1) & 15;
            const float4 na0 = *reinterpret_cast<const float4*>(&As[cur][kn][ty * 8]);
            const float4 na1 = *reinterpret_cast<const float4*>(&As[cur][kn][ty * 8 + 4]);
            const ulonglong2 nbl = *reinterpret_cast<const ulonglong2*>(&Bs[cur][kn][tx * 4]);
            const ulonglong2 nbh = *reinterpret_cast<const ulonglong2*>(&Bs[cur][kn][64 + tx * 4]);
            unsigned long long ap[8];
            ap[0] = bcast2(ca0.x); ap[1] = bcast2(ca0.y);
            ap[2] = bcast2(ca0.z); ap[3] = bcast2(ca0.w);
            ap[4] = bcast2(ca1.x); ap[5] = bcast2(ca1.y);
            ap[6] = bcast2(ca1.z); ap[7] = bcast2(ca1.w);
            #pragma unroll
            for (int i = 0; i < 8; i++) ffma2(acc[i][0], ap[i], cbl.x);
            #pragma unroll
            for (int i = 0; i < 8; i++) ffma2(acc[i][1], ap[i], cbl.y);
            #pragma unroll
            for (int i = 0; i < 8; i++) ffma2(acc[i][2], ap[i], cbh.x);
            #pragma unroll
            for (int i = 0; i < 8; i++) ffma2(acc[i][3], ap[i], cbh.y);
            ca0 = na0; ca1 = na1; cbl = nbl; cbh = nbh;
        }
        if (more) {
            store_a(cur ^ 1);
            if (GUARD) store_b_guard(cur ^ 1);
            else CP_WAIT0();
            __syncthreads();
        }
    }

    #pragma unroll
    for (int i = 0; i < 8; i++) {
        const int gm = m0 + ty * 8 + i;
        if (GUARD && gm >= M) continue;
        int rr = gm;
        if (MAP_ROWS) rr = (gm / 44) * PES + z * PS + (gm % 44);
        float dd = 0.f, sc = 0.f; int sel = 0;
        if (EP == EP_LOGITS) {
            const float w = v1[gm];
            sel = (w > 0.7f) ? 0 : ((w >= 0.3f) ? 1 : 2);
            dd = v2[gm];
            sc = scale_ptr[0];
        }
        float* crow = Cb + (long long)rr * ldc;
        #pragma unroll
        for (int p = 0; p < 4; p++) {
            const int gn0 = n0 + ((p < 2) ? (tx * 4 + p * 2) : (64 + tx * 4 + (p - 2) * 2));
            const uint2 u = *reinterpret_cast<const uint2*>(&acc[i][p]);
            #pragma unroll
            for (int h = 0; h < 2; h++) {
                const int gn = gn0 + h;
                if (GUARD && gn >= N) continue;
                float v = __uint_as_float(h ? u.y : u.x);
                if (EP == EP_BIAS) {
                    v += v1[z * biasStride + gn];
                } else if (EP == EP_BIAS_GELU) {
                    v = gelu_exact(v + v1[z * biasStride + gn]);
                } else if (EP == EP_LOGITS) {
                    v = ((gn / PS) == sel) ? sc * (v + dd) : 0.f;
                }
                crow[gn] = v;
            }
        }
    }
}

// ---------------- dual-GEMM dispatch (unguarded, runtime ep/map) ----------------
struct GDesc {
    const float* A; const float* B; float* C;
    int K, lda, ldb, ldc;
    long long sA, sB, sC;
    const float* v1;
    int biasStride, kChunk;
    int gx, gy;          // tiles in M, N; z = id / (gx*gy)
    int ep, mapRows;
};

__global__ __launch_bounds__(256)
void fgemm_dual(GDesc d0, GDesc d1, int n0)
{
    GDesc d;
    int id = blockIdx.x;
    if (id < n0) { d = d0; }
    else         { d = d1; id -= n0; }
    const int bx = id % d.gx;
    const int t2 = id / d.gx;
    const int by = t2 % d.gy;
    const int z  = t2 / d.gy;

    const float* Ab = d.A + (long long)z * d.sA;
    const float* Bb = d.B + (long long)z * d.sB;
    float*       Cb = d.C + (long long)z * d.sC;

    int ks = 0, ke = d.K;
    if (d.kChunk > 0) {
        ks = z * d.kChunk;
        ke = (d.K < ks + d.kChunk) ? d.K : (ks + d.kChunk);
    }

    __shared__ __align__(16) float As[2][16][128];
    __shared__ __align__(16) float Bs[2][16][128];

    const int tid = threadIdx.x;
    const int tx = tid & 15;
    const int ty = tid >> 4;
    const int m0 = bx * 128;
    const int nn0 = by * 128;

    unsigned long long acc[8][4];
    #pragma unroll
    for (int i = 0; i < 8; i++)
        #pragma unroll
        for (int p = 0; p < 4; p++) acc[i][p] = 0ull;

    const int a_r  = tid >> 1;
    const int a_c8 = (tid & 1) * 8;
    const int t_k = tid >> 4;
    const int t_c = (tid & 15) * 8;

    long long a_off;
    {
        const int gm = m0 + a_r;
        int rr = gm;
        if (d.mapRows) rr = (gm / 44) * PES + z * PS + (gm % 44);
        a_off = (long long)rr * d.lda;
    }

    const uint32_t bsu0 = smem_u32(&Bs[0][t_k][t_c]);
    const uint32_t bsu1 = smem_u32(&Bs[1][t_k][t_c]);

    const int nk = (ke - ks + 15) >> 4;
    float va[8];

    auto load_a = [&](int k0) {
        const float4 u0 = *reinterpret_cast<const float4*>(Ab + a_off + k0 + a_c8);
        const float4 u1 = *reinterpret_cast<const float4*>(Ab + a_off + k0 + a_c8 + 4);
        va[0]=u0.x; va[1]=u0.y; va[2]=u0.z; va[3]=u0.w;
        va[4]=u1.x; va[5]=u1.y; va[6]=u1.z; va[7]=u1.w;
    };
    auto store_a = [&](int buf) {
        #pragma unroll
        for (int j = 0; j < 8; j++) As[buf][a_c8 + j][a_r] = va[j];
    };
    auto cp_b = [&](int k0, int buf) {
        const int gk = k0 + t_k;
        const float* src = Bb + (long long)gk * d.ldb + nn0 + t_c;
        const uint32_t ds = buf ? bsu1 : bsu0;
        cp_async16(ds, src);
        cp_async16(ds + 16, src + 4);
    };

    load_a(ks);
    cp_b(ks, 0);
    CP_COMMIT();
    store_a(0);
    CP_WAIT0();
    __syncthreads();

    for (int kt = 0; kt < nk; kt++) {
        const int cur = kt & 1;
        const bool more = (kt + 1 < nk);
        if (more) {
            const int k0n = ks + ((kt + 1) << 4);
            cp_b(k0n, cur ^ 1);
            CP_COMMIT();
            load_a(k0n);
        }
        float4 ca0 = *reinterpret_cast<const float4*>(&As[cur][0][ty * 8]);
        float4 ca1 = *reinterpret_cast<const float4*>(&As[cur][0][ty * 8 + 4]);
        ulonglong2 cbl = *reinterpret_cast<const ulonglong2*>(&Bs[cur][0][tx * 4]);
        ulonglong2 cbh = *reinterpret_cast<const ulonglong2*>(&Bs[cur][0][64 + tx * 4]);
        #pragma unroll
        for (int k = 0; k < 16; k++) {
            const int kn = (k + 1) & 15;
            const float4 na0 = *reinterpret_cast<const float4*>(&As[cur][kn][ty * 8]);
            const float4 na1 = *reinterpret_cast<const float4*>(&As[cur][kn][ty * 8 + 4]);
            const ulonglong2 nbl = *reinterpret_cast<const ulonglong2*>(&Bs[cur][kn][tx * 4]);
            const ulonglong2 nbh = *reinterpret_cast<const ulonglong2*>(&Bs[cur][kn][64 + tx * 4]);
            unsigned long long ap[8];
            ap[0] = bcast2(ca0.x); ap[1] = bcast2(ca0.y);
            ap[2] = bcast2(ca0.z); ap[3] = bcast2(ca0.w);
            ap[4] = bcast2(ca1.x); ap[5] = bcast2(ca1.y);
            ap[6] = bcast2(ca1.z); ap[7] = bcast2(ca1.w);
            #pragma unroll
            for (int i = 0; i < 8; i++) ffma2(acc[i][0], ap[i], cbl.x);
            #pragma unroll
            for (int i = 0; i < 8; i++) ffma2(acc[i][1], ap[i], cbl.y);
            #pragma unroll
            for (int i = 0; i < 8; i++) ffma2(acc[i][2], ap[i], cbh.x);
            #pragma unroll
            for (int i = 0; i < 8; i++) ffma2(acc[i][3], ap[i], cbh.y);
            ca0 = na0; ca1 = na1; cbl = nbl; cbh = nbh;
        }
        if (more) {
            store_a(cur ^ 1);
            CP_WAIT0();
            __syncthreads();
        }
    }

    #pragma unroll
    for (int i = 0; i < 8; i++) {
        const int gm = m0 + ty * 8 + i;
        int rr = gm;
        if (d.mapRows) rr = (gm / 44) * PES + z * PS + (gm % 44);
        float* crow = Cb + (long long)rr * d.ldc;
        #pragma unroll
        for (int p = 0; p < 4; p++) {
            const int gn0 = nn0 + ((p < 2) ? (tx * 4 + p * 2) : (64 + tx * 4 + (p - 2) * 2));
            const uint2 u = *reinterpret_cast<const uint2*>(&acc[i][p]);
            #pragma unroll
            for (int h = 0; h < 2; h++) {
                const int gn = gn0 + h;
                float v = __uint_as_float(h ? u.y : u.x);
                if (d.ep == EP_BIAS)           v += d.v1[z * d.biasStride + gn];
                else if (d.ep == EP_BIAS_GELU) v = gelu_exact(v + d.v1[z * d.biasStride + gn]);
                crow[gn] = v;
            }
        }
    }
}

// ---------------- split-K reduce ----------------
template<int EP>
__global__ void k_reduceK(const float* __restrict__ part, float* __restrict__ out,
                          int total, int N, long long stride, int nz,
                          const float* __restrict__ bias, int ldcOut)
{
    const int i = blockIdx.x * 256 + threadIdx.x;
    if (i >= total) return;
    float s = 0.f;
    for (int zz = 0; zz < nz; zz++) s += part[(long long)zz * stride + i];
    const int col = i % N;
    if (EP == EP_BIAS)           s += bias[col];
    else if (EP == EP_BIAS_GELU) s = gelu_exact(s + bias[col]);
    out[(long long)(i / N) * ldcOut + col] = s;
}

// ---------------- logits tail: cols 128..131 ----------------
__global__ void k_logits_tail(const float* __restrict__ img_n,
                              const float* __restrict__ mu_cat,
                              const float* __restrict__ attn,
                              const float* __restrict__ dot,
                              const float* __restrict__ scale_ptr,
                              float* __restrict__ logits)
{
    const int row = blockIdx.x * 8 + (threadIdx.x >> 5);
    const int l = threadIdx.x & 31;
    float* orow = logits + (long long)row * PES + 128;
    const float w = attn[row];
    if (!(w < 0.3f)) {
        if (l < 4) orow[l] = 0.f;
        return;
    }
    const float* a = img_n + (long long)row * PD;
    float a0 = 0.f, a1 = 0.f, a2 = 0.f, a3 = 0.f;
    for (int k = l; k < PD; k += 32) {
        const float av = a[k];
        const float* mrow = mu_cat + k * PMUP + 128;
        a0 += av * mrow[0];
        a1 += av * mrow[1];
        a2 += av * mrow[2];
        a3 += av * mrow[3];
    }
    for (int o = 16; o; o >>= 1) {
        a0 += __shfl_xor_sync(~0u, a0, o);
        a1 += __shfl_xor_sync(~0u, a1, o);
        a2 += __shfl_xor_sync(~0u, a2, o);
        a3 += __shfl_xor_sync(~0u, a3, o);
    }
    if (l == 0) {
        const float sc = scale_ptr[0];
        const float dd = dot[row];
        orow[0] = sc * (a0 + dd);
        orow[1] = sc * (a1 + dd);
        orow[2] = sc * (a2 + dd);
        orow[3] = sc * (a3 + dd);
    }
}

// ---------------- slot_in tail: rows 128..131 per batch ----------------
__global__ void k_slotin_tail(const float* __restrict__ dispT,
                              const float* __restrict__ x,
                              float* __restrict__ slot_in)
{
    const int b = blockIdx.x;
    const int t = threadIdx.x;
    const float* img = x + (long long)b * 129 * PD + PD;
    const float* wrow = dispT + (long long)b * PES * PN + 128 * PN;
    __shared__ float wsh[4][PN];
    for (int i = t; i < 4 * PN; i += 256) wsh[i >> 7][i & 127] = wrow[i];
    __syncthreads();
    for (int d = t; d < PD; d += 256) {
        float a0 = 0.f, a1 = 0.f, a2 = 0.f, a3 = 0.f;
        #pragma unroll 4
        for (int n = 0; n < PN; n++) {
            const float v = img[(long long)n * PD + d];
            a0 += wsh[0][n] * v;
            a1 += wsh[1][n] * v;
            a2 += wsh[2][n] * v;
            a3 += wsh[3][n] * v;
        }
        float* o = slot_in + (long long)b * PES * PD + (long long)128 * PD + d;
        o[0]      = a0;
        o[PD]     = a1;
        o[2 * PD] = a2;
        o[3 * PD] = a3;
    }
}

// ---------------- mu rearrange (padded ld 144) ----------------
__global__ void k_prep_mu(const float* __restrict__ mu, float* __restrict__ mu_cat) {
    int idx = blockIdx.x * blockDim.x + threadIdx.x;
    if (idx >= PD * PES) return;
    int d = idx / PES, j = idx % PES;
    int e = j / PS, s = j % PS;
    mu_cat[d * PMUP + j] = mu[((long long)e * PD + d) * PMAXS + s];
}

// ---------------- slot_input = [cls, mean(attn)] ----------------
__global__ void k_build_slotinput(const float* __restrict__ x,
                                  const float* __restrict__ attn,
                                  float* __restrict__ si) {
    int b = blockIdx.x;
    int t = threadIdx.x;
    __shared__ float red[8];
    float s = (t < PN) ? attn[b * PN + t] : 0.f;
    for (int o = 16; o; o >>= 1) s += __shfl_xor_sync(~0u, s, o);
    if ((t & 31) == 0) red[t >> 5] = s;
    __syncthreads();
    const float* cls = x + (long long)b * 129 * PD;
    float* o = si + (long long)b * 769;
    for (int d = t; d < PD; d += 256) o[d] = cls[d];
    if (t == 0) {
        float m = 0.f;
        #pragma unroll
        for (int i = 0; i < 8; i++) m += red[i];
        o[PD] = m * (1.f / (float)PN);
    }
}

// ---------------- LayerNorm + dot: warp-per-row, float4 ----------------
__global__ void k_ln_dot(const float* __restrict__ x,
                         const float* __restrict__ gamma,
                         const float* __restrict__ beta,
                         const float* __restrict__ slot_bias,
                         float* __restrict__ img_n,
                         float* __restrict__ dot) {
    const int m = blockIdx.x * 8 + (threadIdx.x >> 5);
    const int l = threadIdx.x & 31;
    const int b = m >> 7;
    const int n = m & 127;
    const float* row = x + ((long long)b * 129 + 1 + n) * PD;
    const float* sb = slot_bias + (long long)b * PD;

    float4 v[6];
    float s = 0.f, sq = 0.f;
    #pragma unroll
    for (int i = 0; i < 6; i++) {
        v[i] = *reinterpret_cast<const float4*>(row + l * 4 + i * 128);
        s  += v[i].x + v[i].y + v[i].z + v[i].w;
        sq += v[i].x * v[i].x + v[i].y * v[i].y + v[i].z * v[i].z + v[i].w * v[i].w;
    }
    #pragma unroll
    for (int o = 16; o; o >>= 1) {
        s  += __shfl_xor_sync(~0u, s, o);
        sq += __shfl_xor_sync(~0u, sq, o);
    }
    const float mean = s * (1.f / (float)PD);
    const float var  = sq * (1.f / (float)PD) - mean * mean;
    const float inv  = rsqrtf(var + 1e-5f);

    float* orow = img_n + (long long)m * PD;
    float dp = 0.f;
    #pragma unroll
    for (int i = 0; i < 6; i++) {
        const int d = l * 4 + i * 128;
        const float4 g = *reinterpret_cast<const float4*>(gamma + d);
        const float4 bb = *reinterpret_cast<const float4*>(beta + d);
        const float4 sv = *reinterpret_cast<const float4*>(sb + d);
        float4 y;
        y.x = (v[i].x - mean) * inv * g.x + bb.x;
        y.y = (v[i].y - mean) * inv * g.y + bb.y;
        y.z = (v[i].z - mean) * inv * g.z + bb.z;
        y.w = (v[i].w - mean) * inv * g.w + bb.w;
        *reinterpret_cast<float4*>(orow + d) = y;
        dp += y.x * sv.x + y.y * sv.y + y.z * sv.z + y.w * sv.w;
    }
    #pragma unroll
    for (int o = 16; o; o >>= 1) dp += __shfl_xor_sync(~0u, dp, o);
    if (l == 0) dot[m] = dp;
}

// ---------------- dispatch softmax -> transposed output ----------------
__global__ void k_dispatch(const float* __restrict__ logits, float* __restrict__ dispT) {
    const int be = blockIdx.x;
    const int b = be / PE, e = be % PE;
    __shared__ float tile[PN][PS];
    __shared__ float csum[PS];
    const int t = threadIdx.x;
    const float* base = logits + (long long)b * PN * PES + e * PS;
    for (int idx = t; idx < PN * PS; idx += 256) {
        const int n = idx / PS, j = idx % PS;
        tile[n][j] = base[(long long)n * PES + j];
    }
    __syncthreads();
    if (t < PS) {
        float mx = -1e30f;
        for (int n = 0; n < PN; n++) mx = fmaxf(mx, tile[n][t]);
        float sm = 0.f;
        for (int n = 0; n < PN; n++) {
            const float ev = expf(tile[n][t] - mx);
            tile[n][t] = ev;
            sm += ev;
        }
        csum[t] = sm;
    }
    __syncthreads();
    float* ob = dispT + (long long)b * PES * PN + (long long)e * PS * PN;
    for (int idx = t; idx < PN * PS; idx += 256) {
        const int j = idx >> 7, n = idx & 127;
        ob[j * PN + n] = tile[n][j] / csum[j];
    }
}

// ---------------- combine softmax (padded ld out) ----------------
__global__ void k_combine(const float* __restrict__ logits, float* __restrict__ comb) {
    const int row = blockIdx.x * 8 + (threadIdx.x >> 5);
    const int l = threadIdx.x & 31;
    if (row >= PM_TOK) return;
    const float* r = logits + (long long)row * PES;
    float vals[5], mx = -1e30f;
    #pragma unroll
    for (int i = 0; i < 5; i++) {
        const int j = l + i * 32;
        vals[i] = (j < PES) ? r[j] : -1e30f;
        mx = fmaxf(mx, vals[i]);
    }
    for (int o = 16; o; o >>= 1) mx = fmaxf(mx, __shfl_xor_sync(~0u, mx, o));
    float s = 0.f;
    #pragma unroll
    for (int i = 0; i < 5; i++) {
        const int j = l + i * 32;
        if (j < PES) { vals[i] = expf(vals[i] - mx); s += vals[i]; }
    }
    for (int o = 16; o; o >>= 1) s += __shfl_xor_sync(~0u, s, o);
    const float inv = 1.f / s;
    float* o = comb + (long long)row * PESP;
    #pragma unroll
    for (int i = 0; i < 5; i++) {
        const int j = l + i * 32;
        if (j < PES) o[j] = vals[i] * inv;
    }
}

// ---------------- launch ----------------
extern "C" void kernel_launch(void* const* d_in, const int* in_sizes, int n_in,
                              void* d_out, int out_size) {
    const float* x      = (const float*)d_in[0];
    const float* attn   = (const float*)d_in[1];
    const float* gamma  = (const float*)d_in[2];
    const float* beta   = (const float*)d_in[3];
    const float* vsg_w  = (const float*)d_in[4];
    const float* vsg_b  = (const float*)d_in[5];
    const float* mu     = (const float*)d_in[6];
    const float* scale  = (const float*)d_in[7];
    const float* w1     = (const float*)d_in[8];
    const float* b1     = (const float*)d_in[9];
    const float* w2     = (const float*)d_in[10];
    const float* b2     = (const float*)d_in[11];
    const float* cw1    = (const float*)d_in[12];
    const float* cb1    = (const float*)d_in[13];
    const float* cw2    = (const float*)d_in[14];
    const float* cb2    = (const float*)d_in[15];
    float* out = (float*)d_out;

    float *p_si, *p_sb, *p_imgn, *p_dot, *p_mu, *p_log, *p_dispT, *p_comb;
    float *p_sin, *p_h, *p_sout, *p_clsh, *p_part;
    cudaGetSymbolAddress((void**)&p_si,    g_slot_input);
    cudaGetSymbolAddress((void**)&p_sb,    g_slot_bias);
    cudaGetSymbolAddress((void**)&p_imgn,  g_img_n);
    cudaGetSymbolAddress((void**)&p_dot,   g_dot);
    cudaGetSymbolAddress((void**)&p_mu,    g_mu_cat);
    cudaGetSymbolAddress((void**)&p_log,   g_logits);
    cudaGetSymbolAddress((void**)&p_dispT, g_dispT);
    cudaGetSymbolAddress((void**)&p_comb,  g_combine);
    cudaGetSymbolAddress((void**)&p_sin,   g_slot_in);
    cudaGetSymbolAddress((void**)&p_h,     g_hbuf);
    cudaGetSymbolAddress((void**)&p_sout,  g_slot_out);
    cudaGetSymbolAddress((void**)&p_clsh,  g_cls_h);
    cudaGetSymbolAddress((void**)&p_part,  g_part);

    // 1. mu -> (768, 144-padded 132)
    k_prep_mu<<<(PD * PES + 255) / 256, 256>>>(mu, p_mu);
    // 2. slot_input
    k_build_slotinput<<<PB, 256>>>(x, attn, p_si);
    // 3. slot_bias: split-K 4 then reduce + bias
    fgemm2<true, false, EP_STORE><<<dim3(2, 6, 4), 256>>>(
        p_si, vsg_w, p_part, PB, PD, 769, 769, PD, PD,
        0, 0, (long long)PB * PD, nullptr, nullptr, nullptr, 0, 208);
    k_reduceK<EP_BIAS><<<(PB * PD + 255) / 256, 256>>>(
        p_part, p_sb, PB * PD, PD, (long long)PB * PD, 4, vsg_b, PD);
    // 4. LayerNorm + dot (warp-per-row)
    k_ln_dot<<<PM_TOK / 8, 256>>>(x, gamma, beta, p_sb, p_imgn, p_dot);
    // 5. logits cols 0..127, tail cols 128..131
    fgemm2<true, false, EP_LOGITS><<<dim3(PM_TOK / 128, 1, 1), 256>>>(
        p_imgn, p_mu, p_log, PM_TOK, PES, PD, PD, PMUP, PES,
        0, 0, 0, attn, p_dot, scale, 0, 0);
    k_logits_tail<<<PM_TOK / 8, 256>>>(p_imgn, p_mu, attn, p_dot, scale, p_log);
    // 6/7. softmaxes
    k_dispatch<<<PB * PE, 256>>>(p_log, p_dispT);
    k_combine<<<PM_TOK / 8, 256>>>(p_log, p_comb);
    // 8. slot_in rows 0..127 batched; rows 128..131 via tail
    fgemm2<true, false, EP_STORE><<<dim3(1, 6, PB), 256>>>(
        p_dispT, x + PD, p_sin, PES, PD, PN, PN, PD, PD,
        (long long)PES * PN, (long long)129 * PD, (long long)PES * PD,
        nullptr, nullptr, nullptr, 0, 0);
    k_slotin_tail<<<PB, 256>>>(p_dispT, x, p_sin);
    // 9. combined: FFN1 (2112 tiles) + cls1 split-K (144 tiles)
    {
        GDesc dF;
        dF.A = p_sin; dF.B = w1; dF.C = p_h;
        dF.K = PD; dF.lda = PD; dF.ldb = PH; dF.ldc = PH;
        dF.sA = 0; dF.sB = (long long)PD * PH; dF.sC = 0;
        dF.v1 = b1; dF.biasStride = PH; dF.kChunk = 0;
        dF.gx = PM_FFN / 128; dF.gy = PH / 128;
        dF.ep = EP_BIAS_GELU; dF.mapRows = 1;
        GDesc dC;
        dC.A = x; dC.B = cw1; dC.C = p_part;
        dC.K = PD; dC.lda = 129 * PD; dC.ldb = 4 * PD; dC.ldc = 4 * PD;
        dC.sA = 0; dC.sB = 0; dC.sC = (long long)PB * 4 * PD;
        dC.v1 = nullptr; dC.biasStride = 0; dC.kChunk = 256;
        dC.gx = 2; dC.gy = 24;
        dC.ep = EP_STORE; dC.mapRows = 0;
        const int n0 = dF.gx * dF.gy * PE;             // 2112
        const int n1 = dC.gx * dC.gy * 3;              // 144
        fgemm_dual<<<n0 + n1, 256>>>(dF, dC, n0);
    }
    k_reduceK<EP_BIAS_GELU><<<(PB * 4 * PD + 255) / 256, 256>>>(
        p_part, p_clsh, PB * 4 * PD, 4 * PD, (long long)PB * 4 * PD, 3, cb1, 4 * PD);
    // 10. combined: FFN2 (1584 tiles) + cls2 split-K (96 tiles)
    {
        GDesc dF;
        dF.A = p_h; dF.B = w2; dF.C = p_sout;
        dF.K = PH; dF.lda = PH; dF.ldb = PD; dF.ldc = PD;
        dF.sA = 0; dF.sB = (long long)PH * PD; dF.sC = 0;
        dF.v1 = b2; dF.biasStride = PD; dF.kChunk = 0;
        dF.gx = PM_FFN / 128; dF.gy = PD / 128;
        dF.ep = EP_BIAS; dF.mapRows = 1;
        GDesc dC;
        dC.A = p_clsh; dC.B = cw2; dC.C = p_part;
        dC.K = 4 * PD; dC.lda = 4 * PD; dC.ldb = PD; dC.ldc = PD;
        dC.sA = 0; dC.sB = 0; dC.sC = (long long)PB * PD;
        dC.v1 = nullptr; dC.biasStride = 0; dC.kChunk = 384;
        dC.gx = 2; dC.gy = 6;
        dC.ep = EP_STORE; dC.mapRows = 0;
        const int n0 = dF.gx * dF.gy * PE;             // 1584
        const int n1 = dC.gx * dC.gy * 8;              // 96
        fgemm_dual<<<n0 + n1, 256>>>(dF, dC, n0);
    }
    k_reduceK<EP_BIAS><<<(PB * PD + 255) / 256, 256>>>(
        p_part, out, PB * PD, PD, (long long)PB * PD, 8, cb2, 129 * PD);
    // 11. img_out[b] = combine[b] @ slot_out[b]
    fgemm2<true, false, EP_STORE><<<dim3(1, 6, PB), 256>>>(
        p_comb, p_sout, out + PD, PN, PD, PES, PESP, PD, PD,
        (long long)PN * PESP, (long long)PES * PD, (long long)129 * PD,
        nullptr, nullptr, nullptr, 0, 0);
}

// round 16
// speedup vs baseline: 1.0592x; 1.0592x over previous
#include <cuda_runtime.h>
#include <cuda_bf16.h>
#include <math.h>
#include <cstdint>

// ---------------- problem constants ----------------
#define PB 256
#define PN 128
#define PD 768
#define PE 3
#define PS 44
#define PES 132
#define PESP 136          // padded combine ld
#define PMUP 144          // padded mu_cat ld
#define PH 1024
#define PMAXS 88
#define PM_TOK (PB*PN)
#define PM_FFN (PB*PS)

// ---------------- scratch (device globals) ----------------
__device__ float g_slot_input[PB * 769];
__device__ float g_slot_bias [PB * PD];
__device__ float g_img_n     [PM_TOK * PD];
__device__ float g_dot       [PM_TOK];
__device__ float g_mu_cat    [PD * PMUP];
__device__ float g_logits    [PM_TOK * PES];
__device__ float g_dispT     [PB * PES * PN];     // (b, 132, 128)
__device__ float g_combine   [PM_TOK * PESP];     // padded ld 136
__device__ float g_slot_in   [PB * PES * PD];
__device__ float g_hbuf      [PB * PES * PH];
__device__ float g_slot_out  [PB * PES * PD];
__device__ float g_cls_h     [PB * 4 * PD];
__device__ float g_part      [3 * PB * 4 * PD];   // split-K partials

// ---------------- helpers ----------------
__device__ __forceinline__ float gelu_exact(float x) {
    return 0.5f * x * (1.0f + erff(x * 0.70710678118654752440f));
}
__device__ __forceinline__ unsigned long long bcast2(float x) {
    unsigned long long r;
    asm("mov.b64 %0, {%1, %1};" : "=l"(r) : "r"(__float_as_uint(x)));
    return r;
}
__device__ __forceinline__ void ffma2(unsigned long long& c,
                                      unsigned long long a,
                                      unsigned long long b) {
    asm("fma.rn.f32x2 %0, %1, %2, %0;" : "+l"(c) : "l"(a), "l"(b));
}
__device__ __forceinline__ uint32_t smem_u32(const void* p) {
    uint32_t a;
    asm("{ .reg .u64 t; cvta.to.shared.u64 t, %1; cvt.u32.u64 %0, t; }" : "=r"(a) : "l"(p));
    return a;
}
__device__ __forceinline__ void cp_async16(uint32_t dst, const void* src) {
    asm volatile("cp.async.cg.shared.global [%0], [%1], 16;" :: "r"(dst), "l"(src));
}
#define CP_COMMIT() asm volatile("cp.async.commit_group;" ::: "memory")
#define CP_WAIT0()  asm volatile("cp.async.wait_group 0;" ::: "memory")

// ---------------- FFMA2 tiled SGEMM, double-buffered + pipelined ----------------
// C[M,N] = A[M,K] @ B[K,N] row-major; batch via blockIdx.z strides.
// MAP_ROWS: row m -> (m/44)*132 + z*44 + m%44 on A & C (expert slicing).
// kChunk > 0: split-K mode — blockIdx.z selects K range; partial C at z*sC.
#define EP_STORE     0
#define EP_BIAS      1
#define EP_BIAS_GELU 2
#define EP_LOGITS    3

// tile: BM=128, BN=128, BK=16; 256 threads; thread tile 8x8.
template<bool GUARD, bool MAP_ROWS, int EP>
__global__ __launch_bounds__(256)
void fgemm2(const float* __restrict__ A, const float* __restrict__ B,
            float* __restrict__ C,
            int M, int N, int K, int lda, int ldb, int ldc,
            long long sA, long long sB, long long sC,
            const float* __restrict__ v1, const float* __restrict__ v2,
            const float* __restrict__ scale_ptr, int biasStride,
            int kChunk)
{
    const int z = blockIdx.z;
    const float* Ab = A + (long long)z * sA;
    const float* Bb = B + (long long)z * sB;
    float*       Cb = C + (long long)z * sC;

    int ks = 0, ke = K;
    if (kChunk > 0) {
        ks = z * kChunk;
        ke = (K < ks + kChunk) ? K : (ks + kChunk);
    }

    __shared__ __align__(16) float As[2][16][128];
    __shared__ __align__(16) float Bs[2][16][128];

    const int tid = threadIdx.x;          // 256
    const int tx = tid & 15;
    const int ty = tid >> 4;
    const int m0 = blockIdx.x * 128;
    const int n0 = blockIdx.y * 128;

    unsigned long long acc[8][4];
    #pragma unroll
    for (int i = 0; i < 8; i++)
        #pragma unroll
        for (int p = 0; p < 4; p++) acc[i][p] = 0ull;

    // A loader: row tid>>1, k-half (tid&1)*8. B loader: k tid>>4, cols (tid&15)*8.
    const int a_r  = tid >> 1;
    const int a_c8 = (tid & 1) * 8;
    const int t_k = tid >> 4;
    const int t_c = (tid & 15) * 8;

    long long a_off = 0;
    bool a_ok = true;
    {
        const int gm = m0 + a_r;
        a_ok = !GUARD || (gm < M);
        int rr = gm;
        if (MAP_ROWS) rr = (gm / 44) * PES + z * PS + (gm % 44);
        a_off = (long long)rr * lda;
    }
    const bool aAlign = ((a_off & 3) == 0);
    const bool bColsOk = !GUARD || (n0 + 128 <= N);

    // cp.async destinations for B (fast path)
    const uint32_t bsu0 = smem_u32(&Bs[0][t_k][t_c]);
    const uint32_t bsu1 = smem_u32(&Bs[1][t_k][t_c]);

    const int nk = (ke - ks + 15) >> 4;
    float va[8], vb[8];

    // k0 = absolute K base of the 16-wide tile
    auto load_a = [&](int k0) {
        const bool kfull = !GUARD || (k0 + 16 <= ke);
        if ((!GUARD) || (a_ok && aAlign && kfull)) {
            const float4 u0 = *reinterpret_cast<const float4*>(Ab + a_off + k0 + a_c8);
            const float4 u1 = *reinterpret_cast<const float4*>(Ab + a_off + k0 + a_c8 + 4);
            va[0]=u0.x; va[1]=u0.y; va[2]=u0.z; va[3]=u0.w;
            va[4]=u1.x; va[5]=u1.y; va[6]=u1.z; va[7]=u1.w;
        } else {
            #pragma unroll
            for (int j = 0; j < 8; j++) {
                const int k = k0 + a_c8 + j;
                va[j] = (a_ok && k < ke) ? Ab[a_off + k] : 0.f;
            }
        }
    };
    auto store_a = [&](int buf) {
        #pragma unroll
        for (int j = 0; j < 8; j++) As[buf][a_c8 + j][a_r] = va[j];
    };
    auto load_b_guard = [&](int k0) {
        const int gk = k0 + t_k;
        const long long ro = (long long)gk * ldb + n0 + t_c;
        if ((gk < ke) && bColsOk && ((ro & 3) == 0)) {
            const float4 u0 = *reinterpret_cast<const float4*>(Bb + ro);
            const float4 u1 = *reinterpret_cast<const float4*>(Bb + ro + 4);
            vb[0]=u0.x; vb[1]=u0.y; vb[2]=u0.z; vb[3]=u0.w;
            vb[4]=u1.x; vb[5]=u1.y; vb[6]=u1.z; vb[7]=u1.w;
        } else {
            #pragma unroll
            for (int j = 0; j < 8; j++) {
                const int gn = n0 + t_c + j;
                vb[j] = (gk < ke && gn < N) ? Bb[(long long)gk * ldb + gn] : 0.f;
            }
        }
    };
    auto store_b_guard = [&](int buf) {
        *reinterpret_cast<float4*>(&Bs[buf][t_k][t_c])     = make_float4(vb[0], vb[1], vb[2], vb[3]);
        *reinterpret_cast<float4*>(&Bs[buf][t_k][t_c + 4]) = make_float4(vb[4], vb[5], vb[6], vb[7]);
    };
    auto cp_b = [&](int k0, int buf) {
        const int gk = k0 + t_k;
        const float* src = Bb + (long long)gk * ldb + n0 + t_c;
        const uint32_t d = buf ? bsu1 : bsu0;
        cp_async16(d, src);
        cp_async16(d + 16, src + 4);
    };

    // ---- prologue: tile 0 ----
    load_a(ks);
    if (GUARD) {
        load_b_guard(ks);
        store_a(0);
        store_b_guard(0);
    } else {
        cp_b(ks, 0);
        CP_COMMIT();
        store_a(0);
        CP_WAIT0();
    }
    __syncthreads();

    for (int kt = 0; kt < nk; kt++) {
        const int cur = kt & 1;
        const bool more = (kt + 1 < nk);
        if (more) {
            const int k0n = ks + ((kt + 1) << 4);
            if (!GUARD) { cp_b(k0n, cur ^ 1); CP_COMMIT(); }
            else load_b_guard(k0n);
            load_a(k0n);
        }
        // ---- compute from buf cur, register-pipelined fragments, b-major order ----
        float4 ca0 = *reinterpret_cast<const float4*>(&As[cur][0][ty * 8]);
        float4 ca1 = *reinterpret_cast<const float4*>(&As[cur][0][ty * 8 + 4]);
        ulonglong2 cbl = *reinterpret_cast<const ulonglong2*>(&Bs[cur][0][tx * 4]);
        ulonglong2 cbh = *reinterpret_cast<const ulonglong2*>(&Bs[cur][0][64 + tx * 4]);
        #pragma unroll
        for (int k = 0; k < 16; k++) {
            const int kn = (k + 1) & 15;
            const float4 na0 = *reinterpret_cast<const float4*>(&As[cur][kn][ty * 8]);
            const float4 na1 = *reinterpret_cast<const float4*>(&As[cur][kn][ty * 8 + 4]);
            const ulonglong2 nbl = *reinterpret_cast<const ulonglong2*>(&Bs[cur][kn][tx * 4]);
            const ulonglong2 nbh = *reinterpret_cast<const ulonglong2*>(&Bs[cur][kn][64 + tx * 4]);
            unsigned long long ap[8];
            ap[0] = bcast2(ca0.x); ap[1] = bcast2(ca0.y);
            ap[2] = bcast2(ca0.z); ap[3] = bcast2(ca0.w);
            ap[4] = bcast2(ca1.x); ap[5] = bcast2(ca1.y);
            ap[6] = bcast2(ca1.z); ap[7] = bcast2(ca1.w);
            #pragma unroll
            for (int i = 0; i < 8; i++) ffma2(acc[i][0], ap[i], cbl.x);
            #pragma unroll
            for (int i = 0; i < 8; i++) ffma2(acc[i][1], ap[i], cbl.y);
            #pragma unroll
            for (int i = 0; i < 8; i++) ffma2(acc[i][2], ap[i], cbh.x);
            #pragma unroll
            for (int i = 0; i < 8; i++) ffma2(acc[i][3], ap[i], cbh.y);
            ca0 = na0; ca1 = na1; cbl = nbl; cbh = nbh;
        }
        if (more) {
            store_a(cur ^ 1);
            if (GUARD) store_b_guard(cur ^ 1);
            else CP_WAIT0();
            __syncthreads();
        }
    }

    // ---- epilogue ----
    #pragma unroll
    for (int i = 0; i < 8; i++) {
        const int gm = m0 + ty * 8 + i;
        if (GUARD && gm >= M) continue;
        int rr = gm;
        if (MAP_ROWS) rr = (gm / 44) * PES + z * PS + (gm % 44);
        float dd = 0.f, sc = 0.f; int sel = 0;
        if (EP == EP_LOGITS) {
            const float w = v1[gm];
            sel = (w > 0.7f) ? 0 : ((w >= 0.3f) ? 1 : 2);
            dd = v2[gm];
            sc = scale_ptr[0];
        }
        float* crow = Cb + (long long)rr * ldc;
        #pragma unroll
        for (int p = 0; p < 4; p++) {
            const int gn0 = n0 + ((p < 2) ? (tx * 4 + p * 2) : (64 + tx * 4 + (p - 2) * 2));
            const uint2 u = *reinterpret_cast<const uint2*>(&acc[i][p]);
            #pragma unroll
            for (int h = 0; h < 2; h++) {
                const int gn = gn0 + h;
                if (GUARD && gn >= N) continue;
                float v = __uint_as_float(h ? u.y : u.x);
                if (EP == EP_BIAS) {
                    v += v1[z * biasStride + gn];
                } else if (EP == EP_BIAS_GELU) {
                    v = gelu_exact(v + v1[z * biasStride + gn]);
                } else if (EP == EP_LOGITS) {
                    v = ((gn / PS) == sel) ? sc * (v + dd) : 0.f;
                }
                crow[gn] = v;
            }
        }
    }
}

// ---------------- split-K reduce: out = sum_z part[z] (+bias) (+gelu) ----------------
template<int EP>
__global__ void k_reduceK(const float* __restrict__ part, float* __restrict__ out,
                          int total, int N, long long stride, int nz,
                          const float* __restrict__ bias, int ldcOut)
{
    const int i = blockIdx.x * 256 + threadIdx.x;
    if (i >= total) return;
    float s = 0.f;
    for (int zz = 0; zz < nz; zz++) s += part[(long long)zz * stride + i];
    const int col = i % N;
    if (EP == EP_BIAS)           s += bias[col];
    else if (EP == EP_BIAS_GELU) s = gelu_exact(s + bias[col]);
    out[(long long)(i / N) * ldcOut + col] = s;
}

// ---------------- logits tail: cols 128..131 (expert 2, slots 40..43) ----------------
__global__ void k_logits_tail(const float* __restrict__ img_n,
                              const float* __restrict__ mu_cat,
                              const float* __restrict__ attn,
                              const float* __restrict__ dot,
                              const float* __restrict__ scale_ptr,
                              float* __restrict__ logits)
{
    const int row = blockIdx.x * 8 + (threadIdx.x >> 5);
    const int l = threadIdx.x & 31;
    float* orow = logits + (long long)row * PES + 128;
    const float w = attn[row];
    if (!(w < 0.3f)) {            // expert sel != 2 -> masked to exact 0
        if (l < 4) orow[l] = 0.f;
        return;
    }
    const float* a = img_n + (long long)row * PD;
    float a0 = 0.f, a1 = 0.f, a2 = 0.f, a3 = 0.f;
    for (int k = l; k < PD; k += 32) {
        const float av = a[k];
        const float* mrow = mu_cat + k * PMUP + 128;
        a0 += av * mrow[0];
        a1 += av * mrow[1];
        a2 += av * mrow[2];
        a3 += av * mrow[3];
    }
    for (int o = 16; o; o >>= 1) {
        a0 += __shfl_xor_sync(~0u, a0, o);
        a1 += __shfl_xor_sync(~0u, a1, o);
        a2 += __shfl_xor_sync(~0u, a2, o);
        a3 += __shfl_xor_sync(~0u, a3, o);
    }
    if (l == 0) {
        const float sc = scale_ptr[0];
        const float dd = dot[row];
        orow[0] = sc * (a0 + dd);
        orow[1] = sc * (a1 + dd);
        orow[2] = sc * (a2 + dd);
        orow[3] = sc * (a3 + dd);
    }
}

// ---------------- slot_in tail: rows 128..131 per batch ----------------
__global__ void k_slotin_tail(const float* __restrict__ dispT,
                              const float* __restrict__ x,
                              float* __restrict__ slot_in)
{
    const int b = blockIdx.x;
    const int t = threadIdx.x;   // 256
    const float* img = x + (long long)b * 129 * PD + PD;
    const float* wrow = dispT + (long long)b * PES * PN + 128 * PN;
    __shared__ float wsh[4][PN];
    for (int i = t; i < 4 * PN; i += 256) wsh[i >> 7][i & 127] = wrow[i];
    __syncthreads();
    for (int d = t; d < PD; d += 256) {
        float a0 = 0.f, a1 = 0.f, a2 = 0.f, a3 = 0.f;
        #pragma unroll 4
        for (int n = 0; n < PN; n++) {
            const float v = img[(long long)n * PD + d];
            a0 += wsh[0][n] * v;
            a1 += wsh[1][n] * v;
            a2 += wsh[2][n] * v;
            a3 += wsh[3][n] * v;
        }
        float* o = slot_in + (long long)b * PES * PD + (long long)128 * PD + d;
        o[0]      = a0;
        o[PD]     = a1;
        o[2 * PD] = a2;
        o[3 * PD] = a3;
    }
}

// ---------------- mu rearrange (padded ld 144) ----------------
__global__ void k_prep_mu(const float* __restrict__ mu, float* __restrict__ mu_cat) {
    int idx = blockIdx.x * blockDim.x + threadIdx.x;
    if (idx >= PD * PES) return;
    int d = idx / PES, j = idx % PES;
    int e = j / PS, s = j % PS;
    mu_cat[d * PMUP + j] = mu[((long long)e * PD + d) * PMAXS + s];
}

// ---------------- slot_input = [cls, mean(attn)] ----------------
__global__ void k_build_slotinput(const float* __restrict__ x,
                                  const float* __restrict__ attn,
                                  float* __restrict__ si) {
    int b = blockIdx.x;
    int t = threadIdx.x;
    __shared__ float red[8];
    float s = (t < PN) ? attn[b * PN + t] : 0.f;
    for (int o = 16; o; o >>= 1) s += __shfl_xor_sync(~0u, s, o);
    if ((t & 31) == 0) red[t >> 5] = s;
    __syncthreads();
    const float* cls = x + (long long)b * 129 * PD;
    float* o = si + (long long)b * 769;
    for (int d = t; d < PD; d += 256) o[d] = cls[d];
    if (t == 0) {
        float m = 0.f;
        #pragma unroll
        for (int i = 0; i < 8; i++) m += red[i];
        o[PD] = m * (1.f / (float)PN);
    }
}

// ---------------- LayerNorm + dot: warp-per-row, float4 ----------------
__global__ void k_ln_dot(const float* __restrict__ x,
                         const float* __restrict__ gamma,
                         const float* __restrict__ beta,
                         const float* __restrict__ slot_bias,
                         float* __restrict__ img_n,
                         float* __restrict__ dot) {
    const int m = blockIdx.x * 8 + (threadIdx.x >> 5);
    const int l = threadIdx.x & 31;
    const int b = m >> 7;
    const int n = m & 127;
    const float* row = x + ((long long)b * 129 + 1 + n) * PD;
    const float* sb = slot_bias + (long long)b * PD;

    float4 v[6];
    float s = 0.f, sq = 0.f;
    #pragma unroll
    for (int i = 0; i < 6; i++) {
        v[i] = *reinterpret_cast<const float4*>(row + l * 4 + i * 128);
        s  += v[i].x + v[i].y + v[i].z + v[i].w;
        sq += v[i].x * v[i].x + v[i].y * v[i].y + v[i].z * v[i].z + v[i].w * v[i].w;
    }
    #pragma unroll
    for (int o = 16; o; o >>= 1) {
        s  += __shfl_xor_sync(~0u, s, o);
        sq += __shfl_xor_sync(~0u, sq, o);
    }
    const float mean = s * (1.f / (float)PD);
    const float var  = sq * (1.f / (float)PD) - mean * mean;
    const float inv  = rsqrtf(var + 1e-5f);

    float* orow = img_n + (long long)m * PD;
    float dp = 0.f;
    #pragma unroll
    for (int i = 0; i < 6; i++) {
        const int d = l * 4 + i * 128;
        const float4 g = *reinterpret_cast<const float4*>(gamma + d);
        const float4 bb = *reinterpret_cast<const float4*>(beta + d);
        const float4 sv = *reinterpret_cast<const float4*>(sb + d);
        float4 y;
        y.x = (v[i].x - mean) * inv * g.x + bb.x;
        y.y = (v[i].y - mean) * inv * g.y + bb.y;
        y.z = (v[i].z - mean) * inv * g.z + bb.z;
        y.w = (v[i].w - mean) * inv * g.w + bb.w;
        *reinterpret_cast<float4*>(orow + d) = y;
        dp += y.x * sv.x + y.y * sv.y + y.z * sv.z + y.w * sv.w;
    }
    #pragma unroll
    for (int o = 16; o; o >>= 1) dp += __shfl_xor_sync(~0u, dp, o);
    if (l == 0) dot[m] = dp;
}

// ---------------- dispatch softmax -> transposed output ----------------
__global__ void k_dispatch(const float* __restrict__ logits, float* __restrict__ dispT) {
    const int be = blockIdx.x;
    const int b = be / PE, e = be % PE;
    __shared__ float tile[PN][PS];
    __shared__ float csum[PS];
    const int t = threadIdx.x;
    const float* base = logits + (long long)b * PN * PES + e * PS;
    for (int idx = t; idx < PN * PS; idx += 256) {
        const int n = idx / PS, j = idx % PS;
        tile[n][j] = base[(long long)n * PES + j];
    }
    __syncthreads();
    if (t < PS) {
        float mx = -1e30f;
        for (int n = 0; n < PN; n++) mx = fmaxf(mx, tile[n][t]);
        float sm = 0.f;
        for (int n = 0; n < PN; n++) {
            const float ev = expf(tile[n][t] - mx);
            tile[n][t] = ev;
            sm += ev;
        }
        csum[t] = sm;
    }
    __syncthreads();
    float* ob = dispT + (long long)b * PES * PN + (long long)e * PS * PN;
    for (int idx = t; idx < PN * PS; idx += 256) {
        const int j = idx >> 7, n = idx & 127;
        ob[j * PN + n] = tile[n][j] / csum[j];
    }
}

// ---------------- combine softmax (padded ld out) ----------------
__global__ void k_combine(const float* __restrict__ logits, float* __restrict__ comb) {
    const int row = blockIdx.x * 8 + (threadIdx.x >> 5);
    const int l = threadIdx.x & 31;
    if (row >= PM_TOK) return;
    const float* r = logits + (long long)row * PES;
    float vals[5], mx = -1e30f;
    #pragma unroll
    for (int i = 0; i < 5; i++) {
        const int j = l + i * 32;
        vals[i] = (j < PES) ? r[j] : -1e30f;
        mx = fmaxf(mx, vals[i]);
    }
    for (int o = 16; o; o >>= 1) mx = fmaxf(mx, __shfl_xor_sync(~0u, mx, o));
    float s = 0.f;
    #pragma unroll
    for (int i = 0; i < 5; i++) {
        const int j = l + i * 32;
        if (j < PES) { vals[i] = expf(vals[i] - mx); s += vals[i]; }
    }
    for (int o = 16; o; o >>= 1) s += __shfl_xor_sync(~0u, s, o);
    const float inv = 1.f / s;
    float* o = comb + (long long)row * PESP;
    #pragma unroll
    for (int i = 0; i < 5; i++) {
        const int j = l + i * 32;
        if (j < PES) o[j] = vals[i] * inv;
    }
}

// ---------------- launch ----------------
extern "C" void kernel_launch(void* const* d_in, const int* in_sizes, int n_in,
                              void* d_out, int out_size) {
    const float* x      = (const float*)d_in[0];
    const float* attn   = (const float*)d_in[1];
    const float* gamma  = (const float*)d_in[2];
    const float* beta   = (const float*)d_in[3];
    const float* vsg_w  = (const float*)d_in[4];
    const float* vsg_b  = (const float*)d_in[5];
    const float* mu     = (const float*)d_in[6];
    const float* scale  = (const float*)d_in[7];
    const float* w1     = (const float*)d_in[8];
    const float* b1     = (const float*)d_in[9];
    const float* w2     = (const float*)d_in[10];
    const float* b2     = (const float*)d_in[11];
    const float* cw1    = (const float*)d_in[12];
    const float* cb1    = (const float*)d_in[13];
    const float* cw2    = (const float*)d_in[14];
    const float* cb2    = (const float*)d_in[15];
    float* out = (float*)d_out;

    float *p_si, *p_sb, *p_imgn, *p_dot, *p_mu, *p_log, *p_dispT, *p_comb;
    float *p_sin, *p_h, *p_sout, *p_clsh, *p_part;
    cudaGetSymbolAddress((void**)&p_si,    g_slot_input);
    cudaGetSymbolAddress((void**)&p_sb,    g_slot_bias);
    cudaGetSymbolAddress((void**)&p_imgn,  g_img_n);
    cudaGetSymbolAddress((void**)&p_dot,   g_dot);
    cudaGetSymbolAddress((void**)&p_mu,    g_mu_cat);
    cudaGetSymbolAddress((void**)&p_log,   g_logits);
    cudaGetSymbolAddress((void**)&p_dispT, g_dispT);
    cudaGetSymbolAddress((void**)&p_comb,  g_combine);
    cudaGetSymbolAddress((void**)&p_sin,   g_slot_in);
    cudaGetSymbolAddress((void**)&p_h,     g_hbuf);
    cudaGetSymbolAddress((void**)&p_sout,  g_slot_out);
    cudaGetSymbolAddress((void**)&p_clsh,  g_cls_h);
    cudaGetSymbolAddress((void**)&p_part,  g_part);

    // 1. mu -> (768, 144-padded 132)
    k_prep_mu<<<(PD * PES + 255) / 256, 256>>>(mu, p_mu);
    // 2. slot_input
    k_build_slotinput<<<PB, 256>>>(x, attn, p_si);
    // 3. slot_bias: split-K 4 then reduce + bias
    fgemm2<true, false, EP_STORE><<<dim3(2, 6, 4), 256>>>(
        p_si, vsg_w, p_part, PB, PD, 769, 769, PD, PD,
        0, 0, (long long)PB * PD, nullptr, nullptr, nullptr, 0, 208);
    k_reduceK<EP_BIAS><<<(PB * PD + 255) / 256, 256>>>(
        p_part, p_sb, PB * PD, PD, (long long)PB * PD, 4, vsg_b, PD);
    // 4. LayerNorm + dot (warp-per-row float4)
    k_ln_dot<<<PM_TOK / 8, 256>>>(x, gamma, beta, p_sb, p_imgn, p_dot);
    // 5. logits cols 0..127, tail cols 128..131
    fgemm2<true, false, EP_LOGITS><<<dim3(PM_TOK / 128, 1, 1), 256>>>(
        p_imgn, p_mu, p_log, PM_TOK, PES, PD, PD, PMUP, PES,
        0, 0, 0, attn, p_dot, scale, 0, 0);
    k_logits_tail<<<PM_TOK / 8, 256>>>(p_imgn, p_mu, attn, p_dot, scale, p_log);
    // 6/7. softmaxes
    k_dispatch<<<PB * PE, 256>>>(p_log, p_dispT);
    k_combine<<<PM_TOK / 8, 256>>>(p_log, p_comb);
    // 8. slot_in rows 0..127 batched; rows 128..131 via tail
    fgemm2<true, false, EP_STORE><<<dim3(1, 6, PB), 256>>>(
        p_dispT, x + PD, p_sin, PES, PD, PN, PN, PD, PD,
        (long long)PES * PN, (long long)129 * PD, (long long)PES * PD,
        nullptr, nullptr, nullptr, 0, 0);
    k_slotin_tail<<<PB, 256>>>(p_dispT, x, p_sin);
    // 9. FFN1 (11264,1024,K=768) per expert
    fgemm2<false, true, EP_BIAS_GELU><<<dim3(PM_FFN / 128, PH / 128, PE), 256>>>(
        p_sin, w1, p_h, PM_FFN, PH, PD, PD, PH, PH,
        0, (long long)PD * PH, 0, b1, nullptr, nullptr, PH, 0);
    // 10. FFN2 (11264,768,K=1024) per expert
    fgemm2<false, true, EP_BIAS><<<dim3(PM_FFN / 128, PD / 128, PE), 256>>>(
        p_h, w2, p_sout, PM_FFN, PD, PH, PH, PD, PD,
        0, (long long)PH * PD, 0, b2, nullptr, nullptr, PD, 0);
    // 11. img_out[b] = combine[b] @ slot_out[b]
    fgemm2<true, false, EP_STORE><<<dim3(1, 6, PB), 256>>>(
        p_comb, p_sout, out + PD, PN, PD, PES, PESP, PD, PD,
        (long long)PN * PESP, (long long)PES * PD, (long long)129 * PD,
        nullptr, nullptr, nullptr, 0, 0);
    // 12. cls1 (256,3072,K=768): split-K 3 then reduce + bias + gelu
    fgemm2<false, false, EP_STORE><<<dim3(2, 24, 3), 256>>>(
        x, cw1, p_part, PB, 4 * PD, PD, 129 * PD, 4 * PD, 4 * PD,
        0, 0, (long long)PB * 4 * PD, nullptr, nullptr, nullptr, 0, 256);
    k_reduceK<EP_BIAS_GELU><<<(PB * 4 * PD + 255) / 256, 256>>>(
        p_part, p_clsh, PB * 4 * PD, 4 * PD, (long long)PB * 4 * PD, 3, cb1, 4 * PD);
    // 13. cls2 (256,768,K=3072): split-K 8 then reduce -> out row 0
    fgemm2<false, false, EP_STORE><<<dim3(2, 6, 8), 256>>>(
        p_clsh, cw2, p_part, PB, PD, 4 * PD, 4 * PD, PD, PD,
        0, 0, (long long)PB * PD, nullptr, nullptr, nullptr, 0, 384);
    k_reduceK<EP_BIAS><<<(PB * PD + 255) / 256, 256>>>(
        p_part, out, PB * PD, PD, (long long)PB * PD, 8, cb2, 129 * PD);
}